// round 3
// baseline (speedup 1.0000x reference)
#include <cuda_runtime.h>

#define LATENT 16
#define HID 512
#define DD 64
#define NB 128
#define NG 128
#define OUTSZ 12610
#define OUTSZ_PAD 12612

// Scratch (device globals — no allocation allowed)
__device__ float g_h0[NB * HID];
__device__ float g_h1[NB * HID];
__device__ float g_wb[NB * OUTSZ_PAD];

typedef unsigned long long u64;

__device__ __forceinline__ u64 pack2(float lo, float hi) {
    u64 r; asm("mov.b64 %0, {%1, %2};" : "=l"(r) : "f"(lo), "f"(hi)); return r;
}
__device__ __forceinline__ void unpack2(u64 v, float& lo, float& hi) {
    asm("mov.b64 {%0, %1}, %2;" : "=f"(lo), "=f"(hi) : "l"(v));
}
// packed fp32 FMA: d = a*b + d  (2 fp32 lanes per instruction -> 2x FFMA rate)
__device__ __forceinline__ void fma2(u64& d, u64 a, u64 b) {
    asm("fma.rn.f32x2 %0, %1, %2, %0;" : "+l"(d) : "l"(a), "l"(b));
}

__device__ __forceinline__ float leaky(float x) { return x > 0.0f ? x : 0.01f * x; }

// fast sin: 2-step Cody-Waite range reduction + MUFU sin (args stay < ~40)
__device__ __forceinline__ float fsin(float x) {
    float k = rintf(x * 0.15915494309189535f);
    x = fmaf(k, -6.28125f, x);
    x = fmaf(k, -1.9353071795864769e-3f, x);
    return __sinf(x);
}

// ---------------------------------------------------------------------------
// Kernel 1: h0 = leaky_relu(z @ hw0 + hb0)    (128 x 512, K=16)
// ---------------------------------------------------------------------------
__global__ void k_h0(const float* __restrict__ z, const float* __restrict__ hw0,
                     const float* __restrict__ hb0) {
    int b = blockIdx.x;
    int j = threadIdx.x;
    const float* zr = z + b * LATENT;
    float acc = hb0[j];
#pragma unroll
    for (int k = 0; k < LATENT; k++) acc = fmaf(zr[k], hw0[k * HID + j], acc);
    g_h0[b * HID + j] = leaky(acc);
}

// ---------------------------------------------------------------------------
// Tiled fp32 GEMM with packed f32x2 FMA: C = act(A @ B + bias)
// Accumulators packed along N (TN must be even).
// ---------------------------------------------------------------------------
template <int BM, int BN, int BK, int TM, int TN, int ACT>
__global__ void __launch_bounds__((BM / TM) * (BN / TN))
gemm_bias(const float* __restrict__ A, const float* __restrict__ B,
          const float* __restrict__ bias, float* __restrict__ C,
          int M, int N, int K, int ldc) {
    __shared__ __align__(16) float As[BK][BM + 4];
    __shared__ __align__(16) float Bs[BK][BN];
    constexpr int TX = BN / TN;
    constexpr int TY = BM / TM;
    constexpr int NT = TX * TY;
    constexpr int TNH = TN / 2;
    int tid = threadIdx.x;
    int tx = tid % TX, ty = tid / TX;
    int m0 = blockIdx.y * BM, n0 = blockIdx.x * BN;

    u64 acc[TM][TNH];
#pragma unroll
    for (int i = 0; i < TM; i++)
#pragma unroll
        for (int j = 0; j < TNH; j++) acc[i][j] = pack2(0.0f, 0.0f);

    for (int k0 = 0; k0 < K; k0 += BK) {
#pragma unroll
        for (int idx = tid; idx < BM * BK; idx += NT) {
            int r = idx / BK, c = idx % BK;
            As[c][r] = A[(m0 + r) * K + k0 + c];
        }
#pragma unroll
        for (int idx = tid; idx < BK * BN; idx += NT) {
            int r = idx / BN, c = idx % BN;
            int n = n0 + c;
            Bs[r][c] = (n < N) ? B[(k0 + r) * N + n] : 0.0f;
        }
        __syncthreads();
#pragma unroll
        for (int k = 0; k < BK; k++) {
            u64 rap[TM], rbp[TNH];
#pragma unroll
            for (int i = 0; i < TM; i++) {
                float v = As[k][ty * TM + i];
                rap[i] = pack2(v, v);
            }
#pragma unroll
            for (int j = 0; j < TNH; j++)
                rbp[j] = *(const u64*)&Bs[k][tx * TN + 2 * j];
#pragma unroll
            for (int i = 0; i < TM; i++)
#pragma unroll
                for (int j = 0; j < TNH; j++) fma2(acc[i][j], rap[i], rbp[j]);
        }
        __syncthreads();
    }

#pragma unroll
    for (int i = 0; i < TM; i++) {
        int m = m0 + ty * TM + i;
#pragma unroll
        for (int j = 0; j < TNH; j++) {
            float lo, hi;
            unpack2(acc[i][j], lo, hi);
            int n = n0 + tx * TN + 2 * j;
            if (n < N) {
                float v = lo + bias[n];
                if (ACT) v = leaky(v);
                C[m * ldc + n] = v;
            }
            if (n + 1 < N) {
                float v = hi + bias[n + 1];
                if (ACT) v = leaky(v);
                C[m * ldc + n + 1] = v;
            }
        }
    }
}

// ---------------------------------------------------------------------------
// Decoder: one block per b, 512 threads. Thread (g = tid&127, part = tid>>7)
// computes 16 of the 64 layer outputs for its g. x vectors ping-pong through
// smem in layout x[i*128 + g] (conflict-free: warp lanes = consecutive g).
//
// Weight smem layout (floats):
//   [0 .. 12288)   : W1,W2,W3 (3 x 64x64 row-major)
//   [12288..12352) : W0
//   [12352..12544) : b1,b2,b3
//   [12544..12608) : W4
//   [12608] b0, [12609] b4
//   [12612 .. +8192) : x buffer A
//   [20804 .. +8192) : x buffer B
// ---------------------------------------------------------------------------
#define OFF_W0 12288
#define OFF_B  12352
#define OFF_W4 12544
#define OFF_XA 12612
#define OFF_XB 20804
#define DEC_SMEM_FLOATS (OFF_XB + DD * NG)   // 28996
#define DEC_SMEM_BYTES (DEC_SMEM_FLOATS * 4) // 115984

__global__ void __launch_bounds__(512)
k_decode(const float* __restrict__ logP, float* __restrict__ out) {
    extern __shared__ __align__(16) float wb[];
    int b = blockIdx.x;
    int tid = threadIdx.x;
    const float* src = g_wb + (size_t)b * OUTSZ_PAD;

    // Repack wb row into aligned smem layout
    for (int l = 0; l < 3; l++)
        for (int i = tid; i < DD * DD; i += 512)
            wb[l * DD * DD + i] = src[65 + l * 4160 + i];
    if (tid < DD) {
        wb[OFF_W0 + tid] = src[tid];
        wb[OFF_B + 0 * DD + tid] = src[4161 + tid];
        wb[OFF_B + 1 * DD + tid] = src[8321 + tid];
        wb[OFF_B + 2 * DD + tid] = src[12481 + tid];
        wb[OFF_W4 + tid] = src[12545 + tid];
    }
    if (tid == 0) { wb[12608] = src[64]; wb[12609] = src[12609]; }
    __syncthreads();

    int g = tid & (NG - 1);
    int part = tid >> 7;        // 0..3
    int j0 = part * 16;

    float xin = logP[b * NG + g];
    float b0 = wb[12608];
    float* xA = wb + OFF_XA;
    float* xB = wb + OFF_XB;

    // First layer: x = sin(30*(xin*W0 + b0)), write to buffer A
#pragma unroll
    for (int jj = 0; jj < 16; jj++) {
        int j = j0 + jj;
        xA[j * NG + g] = fsin(30.0f * fmaf(xin, wb[OFF_W0 + j], b0));
    }
    __syncthreads();

    // 3 hidden decoder layers: A->B->A->B
#pragma unroll 1
    for (int it = 0; it < 3; it++) {
        const float* W = wb + it * DD * DD;
        const float* bs = wb + OFF_B + it * DD;
        const float* xi = (it & 1) ? xB : xA;
        float* xo = (it & 1) ? xA : xB;

        u64 a[8];
#pragma unroll
        for (int m = 0; m < 8; m++)
            a[m] = pack2(bs[j0 + 2 * m], bs[j0 + 2 * m + 1]);

#pragma unroll
        for (int i = 0; i < DD; i++) {
            float xv = xi[i * NG + g];
            u64 xp = pack2(xv, xv);
            const ulonglong2* wp = (const ulonglong2*)(W + i * DD + j0);
            ulonglong2 w0 = wp[0], w1 = wp[1], w2 = wp[2], w3 = wp[3];
            fma2(a[0], xp, w0.x); fma2(a[1], xp, w0.y);
            fma2(a[2], xp, w1.x); fma2(a[3], xp, w1.y);
            fma2(a[4], xp, w2.x); fma2(a[5], xp, w2.y);
            fma2(a[6], xp, w3.x); fma2(a[7], xp, w3.y);
        }
#pragma unroll
        for (int m = 0; m < 8; m++) {
            float lo, hi;
            unpack2(a[m], lo, hi);
            xo[(j0 + 2 * m) * NG + g] = fsin(lo);
            xo[(j0 + 2 * m + 1) * NG + g] = fsin(hi);
        }
        __syncthreads();
    }

    // Final layer: dot(x, W4) + b4 — part 0 threads only (one per g)
    if (tid < NG) {
        float acc = wb[12609];
#pragma unroll
        for (int i = 0; i < DD; i++)
            acc = fmaf(xB[i * NG + tid], wb[OFF_W4 + i], acc);
        out[b * NG + tid] = fmaf(acc, 500.0f, 1500.0f);
    }
}

// ---------------------------------------------------------------------------
extern "C" void kernel_launch(void* const* d_in, const int* in_sizes, int n_in,
                              void* d_out, int out_size) {
    (void)in_sizes; (void)n_in; (void)out_size;
    const float* z    = (const float*)d_in[0];
    const float* logP = (const float*)d_in[1];
    const float* hw0  = (const float*)d_in[2];
    const float* hb0  = (const float*)d_in[3];
    const float* hw1  = (const float*)d_in[4];
    const float* hb1  = (const float*)d_in[5];
    const float* hw2  = (const float*)d_in[6];
    const float* hb2  = (const float*)d_in[7];
    float* out = (float*)d_out;

    float *p_h0, *p_h1, *p_wb;
    cudaGetSymbolAddress((void**)&p_h0, g_h0);
    cudaGetSymbolAddress((void**)&p_h1, g_h1);
    cudaGetSymbolAddress((void**)&p_wb, g_wb);

    cudaFuncSetAttribute(k_decode, cudaFuncAttributeMaxDynamicSharedMemorySize,
                         DEC_SMEM_BYTES);

    // 1) h0 = leaky(z @ hw0 + hb0)
    k_h0<<<NB, HID>>>(z, hw0, hb0);

    // 2) h1 = leaky(h0 @ hw1 + hb1)   M=128,N=512,K=512
    {
        dim3 grid(HID / 32, NB / 32);
        gemm_bias<32, 32, 32, 2, 2, 1><<<grid, 256>>>(p_h0, hw1, hb1, p_h1,
                                                      NB, HID, HID, HID);
    }

    // 3) wb = h1 @ hw2 + hb2          M=128,N=12610,K=512
    {
        dim3 grid((OUTSZ + 127) / 128, NB / 32);
        gemm_bias<32, 128, 16, 4, 8, 0><<<grid, 128>>>(p_h1, hw2, hb2, p_wb,
                                                       NB, OUTSZ, HID, OUTSZ_PAD);
    }

    // 4) decoder
    k_decode<<<NB, 512, DEC_SMEM_BYTES>>>(logP, out);
}

// round 4
// speedup vs baseline: 1.2842x; 1.2842x over previous
#include <cuda_runtime.h>

#define LATENT 16
#define HID 512
#define DD 64
#define NB 128
#define NG 128
#define OUTSZ 12610
#define OUTSZ_PAD 12612

// Scratch (device globals — no allocation allowed)
__device__ float g_h0[NB * HID];
__device__ float g_h1[NB * HID];
__device__ float g_wb[NB * OUTSZ_PAD];

typedef unsigned long long u64;

__device__ __forceinline__ u64 pack2(float lo, float hi) {
    u64 r; asm("mov.b64 %0, {%1, %2};" : "=l"(r) : "f"(lo), "f"(hi)); return r;
}
__device__ __forceinline__ void unpack2(u64 v, float& lo, float& hi) {
    asm("mov.b64 {%0, %1}, %2;" : "=f"(lo), "=f"(hi) : "l"(v));
}
// packed fp32 FMA: d = a*b + d  (2 fp32 lanes per instruction)
__device__ __forceinline__ void fma2(u64& d, u64 a, u64 b) {
    asm("fma.rn.f32x2 %0, %1, %2, %0;" : "+l"(d) : "l"(a), "l"(b));
}

__device__ __forceinline__ float leaky(float x) { return x > 0.0f ? x : 0.01f * x; }

// fast sin: 2-step Cody-Waite range reduction + MUFU sin (args stay < ~40)
__device__ __forceinline__ float fsin(float x) {
    float k = rintf(x * 0.15915494309189535f);
    x = fmaf(k, -6.28125f, x);
    x = fmaf(k, -1.9353071795864769e-3f, x);
    return __sinf(x);
}

// ---------------------------------------------------------------------------
// Kernel 1: h0 = leaky_relu(z @ hw0 + hb0)    (128 x 512, K=16)
// ---------------------------------------------------------------------------
__global__ void k_h0(const float* __restrict__ z, const float* __restrict__ hw0,
                     const float* __restrict__ hb0) {
    int b = blockIdx.x;
    int j = threadIdx.x;
    const float* zr = z + b * LATENT;
    float acc = hb0[j];
#pragma unroll
    for (int k = 0; k < LATENT; k++) acc = fmaf(zr[k], hw0[k * HID + j], acc);
    g_h0[b * HID + j] = leaky(acc);
}

// ---------------------------------------------------------------------------
// Tiled fp32 GEMM, packed f32x2 FMA, conflict-free fragment layout.
// Thread grid: TX=16 (columns) x TY=NT/16 (rows).
// Each thread owns TNH u64 accumulator columns at n = n0 + tx*2 + j*32
// (strided: a warp's LDS.64 covers 128 contiguous bytes -> conflict-free),
// and TM = BM/TY rows (warp-broadcast A reads).
// ---------------------------------------------------------------------------
template <int BM, int BN, int BK, int NT, int ACT>
__global__ void __launch_bounds__(NT)
gemm_bias(const float* __restrict__ A, const float* __restrict__ B,
          const float* __restrict__ bias, float* __restrict__ C,
          int M, int N, int K, int ldc) {
    constexpr int TY = NT / 16;
    constexpr int TM = BM / TY;
    constexpr int TNH = BN / 32;   // u64 columns per thread
    __shared__ __align__(16) float As[BK][BM + 4];
    __shared__ __align__(16) float Bs[BK][BN];

    int tid = threadIdx.x;
    int tx = tid & 15, ty = tid >> 4;
    int m0 = blockIdx.y * BM, n0 = blockIdx.x * BN;

    u64 acc[TM][TNH];
#pragma unroll
    for (int i = 0; i < TM; i++)
#pragma unroll
        for (int j = 0; j < TNH; j++) acc[i][j] = pack2(0.0f, 0.0f);

    for (int k0 = 0; k0 < K; k0 += BK) {
        // A tile: float4 along K, transposed store into As[k][m]
#pragma unroll
        for (int idx = tid; idx < BM * BK / 4; idx += NT) {
            int r = idx / (BK / 4), c4 = idx % (BK / 4);
            float4 v = *(const float4*)&A[(size_t)(m0 + r) * K + k0 + c4 * 4];
            As[c4 * 4 + 0][r] = v.x;
            As[c4 * 4 + 1][r] = v.y;
            As[c4 * 4 + 2][r] = v.z;
            As[c4 * 4 + 3][r] = v.w;
        }
        // B tile: scalar coalesced (N not 16B-divisible), guarded
#pragma unroll
        for (int idx = tid; idx < BK * BN; idx += NT) {
            int r = idx / BN, c = idx % BN;
            int n = n0 + c;
            Bs[r][c] = (n < N) ? B[(size_t)(k0 + r) * N + n] : 0.0f;
        }
        __syncthreads();
#pragma unroll
        for (int k = 0; k < BK; k++) {
            u64 rap[TM], rbp[TNH];
#pragma unroll
            for (int i = 0; i < TM; i++) {
                float v = As[k][ty * TM + i];
                rap[i] = pack2(v, v);
            }
#pragma unroll
            for (int j = 0; j < TNH; j++)
                rbp[j] = *(const u64*)&Bs[k][tx * 2 + j * 32];
#pragma unroll
            for (int i = 0; i < TM; i++)
#pragma unroll
                for (int j = 0; j < TNH; j++) fma2(acc[i][j], rap[i], rbp[j]);
        }
        __syncthreads();
    }

#pragma unroll
    for (int i = 0; i < TM; i++) {
        int m = m0 + ty * TM + i;
#pragma unroll
        for (int j = 0; j < TNH; j++) {
            float lo, hi;
            unpack2(acc[i][j], lo, hi);
            int n = n0 + tx * 2 + j * 32;
            if (n < N) {
                float v = lo + bias[n];
                if (ACT) v = leaky(v);
                C[(size_t)m * ldc + n] = v;
            }
            if (n + 1 < N) {
                float v = hi + bias[n + 1];
                if (ACT) v = leaky(v);
                C[(size_t)m * ldc + n + 1] = v;
            }
        }
    }
}

// ---------------------------------------------------------------------------
// Decoder: one block per b, 512 threads. Thread (g = tid&127, part = tid>>7)
// computes 16 of the 64 layer outputs for its g; x ping-pongs through smem
// in layout x[i*128 + g] (conflict-free; W reads are warp-broadcast).
// ---------------------------------------------------------------------------
#define OFF_W0 12288
#define OFF_B  12352
#define OFF_W4 12544
#define OFF_XA 12612
#define OFF_XB 20804
#define DEC_SMEM_FLOATS (OFF_XB + DD * NG)
#define DEC_SMEM_BYTES (DEC_SMEM_FLOATS * 4)

__global__ void __launch_bounds__(512)
k_decode(const float* __restrict__ logP, float* __restrict__ out) {
    extern __shared__ __align__(16) float wb[];
    int b = blockIdx.x;
    int tid = threadIdx.x;
    const float* src = g_wb + (size_t)b * OUTSZ_PAD;

    // Repack wb row into aligned smem layout
    for (int l = 0; l < 3; l++)
        for (int i = tid; i < DD * DD; i += 512)
            wb[l * DD * DD + i] = src[65 + l * 4160 + i];
    if (tid < DD) {
        wb[OFF_W0 + tid] = src[tid];
        wb[OFF_B + 0 * DD + tid] = src[4161 + tid];
        wb[OFF_B + 1 * DD + tid] = src[8321 + tid];
        wb[OFF_B + 2 * DD + tid] = src[12481 + tid];
        wb[OFF_W4 + tid] = src[12545 + tid];
    }
    if (tid == 0) { wb[12608] = src[64]; wb[12609] = src[12609]; }
    __syncthreads();

    int g = tid & (NG - 1);
    int part = tid >> 7;
    int j0 = part * 16;

    float xin = logP[b * NG + g];
    float b0 = wb[12608];
    float* xA = wb + OFF_XA;
    float* xB = wb + OFF_XB;

#pragma unroll
    for (int jj = 0; jj < 16; jj++) {
        int j = j0 + jj;
        xA[j * NG + g] = fsin(30.0f * fmaf(xin, wb[OFF_W0 + j], b0));
    }
    __syncthreads();

#pragma unroll 1
    for (int it = 0; it < 3; it++) {
        const float* W = wb + it * DD * DD;
        const float* bs = wb + OFF_B + it * DD;
        const float* xi = (it & 1) ? xB : xA;
        float* xo = (it & 1) ? xA : xB;

        u64 a[8];
#pragma unroll
        for (int m = 0; m < 8; m++)
            a[m] = pack2(bs[j0 + 2 * m], bs[j0 + 2 * m + 1]);

#pragma unroll
        for (int i = 0; i < DD; i++) {
            float xv = xi[i * NG + g];
            u64 xp = pack2(xv, xv);
            const ulonglong2* wp = (const ulonglong2*)(W + i * DD + j0);
            ulonglong2 w0 = wp[0], w1 = wp[1], w2 = wp[2], w3 = wp[3];
            fma2(a[0], xp, w0.x); fma2(a[1], xp, w0.y);
            fma2(a[2], xp, w1.x); fma2(a[3], xp, w1.y);
            fma2(a[4], xp, w2.x); fma2(a[5], xp, w2.y);
            fma2(a[6], xp, w3.x); fma2(a[7], xp, w3.y);
        }
#pragma unroll
        for (int m = 0; m < 8; m++) {
            float lo, hi;
            unpack2(a[m], lo, hi);
            xo[(j0 + 2 * m) * NG + g] = fsin(lo);
            xo[(j0 + 2 * m + 1) * NG + g] = fsin(hi);
        }
        __syncthreads();
    }

    if (tid < NG) {
        float acc = wb[12609];
#pragma unroll
        for (int i = 0; i < DD; i++)
            acc = fmaf(xB[i * NG + tid], wb[OFF_W4 + i], acc);
        out[b * NG + tid] = fmaf(acc, 500.0f, 1500.0f);
    }
}

// ---------------------------------------------------------------------------
extern "C" void kernel_launch(void* const* d_in, const int* in_sizes, int n_in,
                              void* d_out, int out_size) {
    (void)in_sizes; (void)n_in; (void)out_size;
    const float* z    = (const float*)d_in[0];
    const float* logP = (const float*)d_in[1];
    const float* hw0  = (const float*)d_in[2];
    const float* hb0  = (const float*)d_in[3];
    const float* hw1  = (const float*)d_in[4];
    const float* hb1  = (const float*)d_in[5];
    const float* hw2  = (const float*)d_in[6];
    const float* hb2  = (const float*)d_in[7];
    float* out = (float*)d_out;

    float *p_h0, *p_h1, *p_wb;
    cudaGetSymbolAddress((void**)&p_h0, g_h0);
    cudaGetSymbolAddress((void**)&p_h1, g_h1);
    cudaGetSymbolAddress((void**)&p_wb, g_wb);

    cudaFuncSetAttribute(k_decode, cudaFuncAttributeMaxDynamicSharedMemorySize,
                         DEC_SMEM_BYTES);

    // 1) h0 = leaky(z @ hw0 + hb0)
    k_h0<<<NB, HID>>>(z, hw0, hb0);

    // 2) h1 = leaky(h0 @ hw1 + hb1)   M=128,N=512,K=512  -> 64 blocks
    {
        dim3 grid(HID / 64, NB / 16);
        gemm_bias<16, 64, 16, 128, 1><<<grid, 128>>>(p_h0, hw1, hb1, p_h1,
                                                     NB, HID, HID, HID);
    }

    // 3) wb = h1 @ hw2 + hb2          M=128,N=12610,K=512 -> 396 blocks
    {
        dim3 grid((OUTSZ + 127) / 128, NB / 32);
        gemm_bias<32, 128, 16, 128, 0><<<grid, 128>>>(p_h1, hw2, hb2, p_wb,
                                                      NB, OUTSZ, HID, OUTSZ_PAD);
    }

    // 4) decoder
    k_decode<<<NB, 512, DEC_SMEM_BYTES>>>(logP, out);
}